// round 17
// baseline (speedup 1.0000x reference)
#include <cuda_runtime.h>
#include <cstdint>

#define NN 100000
#define EE 1600000
#define NODE_DIM 128
#define HC 32          // heads * channels
#define NHEAD 2
#define NEG_SLOPE 0.2f
#define NB 391         // (NN + 255) / 256  scan blocks

// ---------------- scratch (device globals; no allocations allowed) ----------
__device__ float g_xl[NN * HC];
__device__ float g_xr[NN * HC];
__device__ float g_h[NN * HC];
__device__ int   g_ideg[NN];
__device__ int   g_offs[NN];      // exclusive prefix of in-degree
__device__ int   g_cursor[NN];
__device__ int   g_bsum[512];
__device__ int   g_boff[512];
__device__ int2  g_csr[EE];       // {src, eattr-bits} grouped by dst

// ================= CSR build =================================================
__global__ void zero_ideg_kernel() {
    int i = blockIdx.x * blockDim.x + threadIdx.x;
    if (i < NN) g_ideg[i] = 0;
}

__global__ void hist_kernel(const int* __restrict__ dst) {
    int e = blockIdx.x * blockDim.x + threadIdx.x;
    if (e < EE) atomicAdd(&g_ideg[dst[e]], 1);
}

// per-block sums of in-degree
__global__ void scan1_kernel() {
    __shared__ int s[256];
    int tid = threadIdx.x;
    int i = blockIdx.x * 256 + tid;
    int v = (i < NN) ? g_ideg[i] : 0;
    s[tid] = v;
    __syncthreads();
    for (int off = 128; off > 0; off >>= 1) {
        if (tid < off) s[tid] += s[tid + off];
        __syncthreads();
    }
    if (tid == 0) g_bsum[blockIdx.x] = s[0];
}

// exclusive scan of the NB block sums (one block)
__global__ void scan2_kernel() {
    __shared__ int s[512];
    int tid = threadIdx.x;
    int v = (tid < NB) ? g_bsum[tid] : 0;
    s[tid] = v;
    __syncthreads();
    for (int off = 1; off < 512; off <<= 1) {
        int t = (tid >= off) ? s[tid - off] : 0;
        __syncthreads();
        s[tid] += t;
        __syncthreads();
    }
    g_boff[tid] = s[tid] - v;   // exclusive
}

// in-block exclusive scan + block base -> g_offs; zero cursors
__global__ void scan3_kernel() {
    __shared__ int s[256];
    int tid = threadIdx.x;
    int i = blockIdx.x * 256 + tid;
    int v = (i < NN) ? g_ideg[i] : 0;
    s[tid] = v;
    __syncthreads();
    for (int off = 1; off < 256; off <<= 1) {
        int t = (tid >= off) ? s[tid - off] : 0;
        __syncthreads();
        s[tid] += t;
        __syncthreads();
    }
    if (i < NN) {
        g_offs[i] = s[tid] - v + g_boff[blockIdx.x];
        g_cursor[i] = 0;
    }
}

__global__ void scatter_kernel(const int* __restrict__ src,
                               const int* __restrict__ dst,
                               const float* __restrict__ eattr) {
    int e = blockIdx.x * blockDim.x + threadIdx.x;
    if (e >= EE) return;
    int d = dst[e];
    int pos = g_offs[d] + atomicAdd(&g_cursor[d], 1);
    g_csr[pos] = make_int2(src[e], __float_as_int(eattr[e]));
}

// ================= tiled projection GEMM =====================================
// C[N x 64] = in[N x D] @ [Wl | Wr] (+ bl|br), split-stored into g_xl / g_xr.
// SRC=0: in = x argument (layer 1, D=128); SRC=1: in = g_h (layer 2, D=32).
template <int D, int SRC>
__global__ void __launch_bounds__(256) proj_gemm(
    const float* __restrict__ x,
    const float* __restrict__ Wl, const float* __restrict__ bl,
    const float* __restrict__ Wr, const float* __restrict__ br)
{
    __shared__ float Ws[D][64];
    __shared__ float xs[64][33];

    const int tid = threadIdx.x;
    const int node0 = blockIdx.x * 64;

    for (int i = tid; i < D * 64; i += 256) {
        int k = i >> 6, c = i & 63;
        Ws[k][c] = (c < 32) ? __ldg(Wl + k * 32 + c) : __ldg(Wr + k * 32 + (c - 32));
    }

    const int c4 = (tid & 15) * 4;
    const int ng = tid >> 4;
    float acc[4][4];
#pragma unroll
    for (int i = 0; i < 4; i++)
#pragma unroll
        for (int j = 0; j < 4; j++) acc[i][j] = 0.f;

#pragma unroll
    for (int k0 = 0; k0 < D; k0 += 32) {
        __syncthreads();
        if (SRC == 0) {
#pragma unroll
            for (int it = 0; it < 2; it++) {
                int j = tid + it * 256;
                int n = j >> 3, f = (j & 7) * 4;
                float4 v = make_float4(0.f, 0.f, 0.f, 0.f);
                int node = node0 + n;
                if (node < NN)
                    v = *(const float4*)(x + (size_t)node * D + k0 + f);
                xs[n][f + 0] = v.x; xs[n][f + 1] = v.y;
                xs[n][f + 2] = v.z; xs[n][f + 3] = v.w;
            }
        } else {
#pragma unroll
            for (int it = 0; it < 2; it++) {
                int j = tid + it * 256;
                int n = j >> 3, f = (j & 7) * 4;
                float4 v = make_float4(0.f, 0.f, 0.f, 0.f);
                int node = node0 + n;
                if (node < NN)
                    v = *(const float4*)&g_h[node * HC + f];
                xs[n][f + 0] = v.x; xs[n][f + 1] = v.y;
                xs[n][f + 2] = v.z; xs[n][f + 3] = v.w;
            }
        }
        __syncthreads();

#pragma unroll
        for (int kk = 0; kk < 32; kk++) {
            float4 b = *(const float4*)&Ws[k0 + kk][c4];
            float a0 = xs[ng * 4 + 0][kk];
            float a1 = xs[ng * 4 + 1][kk];
            float a2 = xs[ng * 4 + 2][kk];
            float a3 = xs[ng * 4 + 3][kk];
            acc[0][0] += a0 * b.x; acc[0][1] += a0 * b.y; acc[0][2] += a0 * b.z; acc[0][3] += a0 * b.w;
            acc[1][0] += a1 * b.x; acc[1][1] += a1 * b.y; acc[1][2] += a1 * b.z; acc[1][3] += a1 * b.w;
            acc[2][0] += a2 * b.x; acc[2][1] += a2 * b.y; acc[2][2] += a2 * b.z; acc[2][3] += a2 * b.w;
            acc[3][0] += a3 * b.x; acc[3][1] += a3 * b.y; acc[3][2] += a3 * b.z; acc[3][3] += a3 * b.w;
        }
    }

    float bv[4];
#pragma unroll
    for (int j = 0; j < 4; j++) {
        int c = c4 + j;
        bv[j] = (c < 32) ? __ldg(bl + c) : __ldg(br + c - 32);
    }
#pragma unroll
    for (int i = 0; i < 4; i++) {
        int node = node0 + ng * 4 + i;
        if (node >= NN) continue;
        float4 v = make_float4(acc[i][0] + bv[0], acc[i][1] + bv[1],
                               acc[i][2] + bv[2], acc[i][3] + bv[3]);
        if (c4 < 32)
            *(float4*)&g_xl[node * HC + c4] = v;
        else
            *(float4*)&g_xr[node * HC + (c4 - 32)] = v;
    }
}

__device__ __forceinline__ float half_reduce16(float t) {
    t += __shfl_xor_sync(0xffffffffu, t, 1);
    t += __shfl_xor_sync(0xffffffffu, t, 2);
    t += __shfl_xor_sync(0xffffffffu, t, 4);
    t += __shfl_xor_sync(0xffffffffu, t, 8);
    return t;
}

// ================= CSR aggregation: warp per destination node ================
// Computes self-loop + all incoming edges, softmax-normalized, writes
// h = num/den + bias directly. No atomics, no extra passes.
__global__ void __launch_bounds__(256) agg_kernel(
    const float* __restrict__ We, const float* __restrict__ att,
    const float* __restrict__ bias)
{
    int n = (blockIdx.x * blockDim.x + threadIdx.x) >> 5;
    int lane = threadIdx.x & 31;
    if (n >= NN) return;

    int row0 = g_offs[n];
    int row1 = (n + 1 < NN) ? g_offs[n + 1] : EE;

    // loop_attr = mean of incoming eattr (lane-parallel row sum)
    float es = 0.f;
    for (int i = row0 + lane; i < row1; i += 32)
        es += __int_as_float(g_csr[i].y);
#pragma unroll
    for (int m = 16; m > 0; m >>= 1)
        es += __shfl_xor_sync(0xffffffffu, es, m);
    float loop_attr = es / fmaxf((float)(row1 - row0), 1.f);

    float Wev  = __ldg(We + lane);
    float attv = __ldg(att + lane);
    float xld  = g_xl[n * HC + lane];
    float xrd  = g_xr[n * HC + lane];

    // self loop
    float v = xld + xrd + loop_attr * Wev;
    v = (v >= 0.f) ? v : NEG_SLOPE * v;
    float a = __expf(half_reduce16(v * attv));
    float num = a * xld;
    float den = a;                 // identical within each 16-lane head half

    // incoming edges (prefetch next CSR entry to break the load chain)
    int2 p = (row0 < row1) ? __ldg(&g_csr[row0]) : make_int2(0, 0);
    for (int i = row0; i < row1; ++i) {
        int2 pn = (i + 1 < row1) ? __ldg(&g_csr[i + 1]) : p;
        float xlv = __ldg(&g_xl[p.x * HC + lane]);      // 128B L2 line
        float vv = xlv + xrd + __int_as_float(p.y) * Wev;
        vv = (vv >= 0.f) ? vv : NEG_SLOPE * vv;
        float aa = __expf(half_reduce16(vv * attv));
        num += aa * xlv;
        den += aa;
        p = pn;
    }

    g_h[n * HC + lane] = num / den + __ldg(bias + lane);
}

// ================= decoder: warp per node ====================================
__global__ void __launch_bounds__(256) decoder_kernel(
    const float* __restrict__ Wd1, const float* __restrict__ bd1,
    const float* __restrict__ Wd2, const float* __restrict__ bd2,
    float* __restrict__ out)
{
    int n = (blockIdx.x * blockDim.x + threadIdx.x) >> 5;
    int lane = threadIdx.x & 31;
    if (n >= NN) return;
    float myh = g_h[n * HC + lane];
    float hid = __ldg(bd1 + lane);
#pragma unroll
    for (int k = 0; k < HC; k++) {
        float hv = __shfl_sync(0xffffffffu, myh, k);
        hid += hv * __ldg(Wd1 + k * HC + lane);
    }
    hid = fmaxf(hid, 0.f);
    float o0 = hid * __ldg(Wd2 + lane * 2 + 0);
    float o1 = hid * __ldg(Wd2 + lane * 2 + 1);
#pragma unroll
    for (int m = 16; m > 0; m >>= 1) {
        o0 += __shfl_xor_sync(0xffffffffu, o0, m);
        o1 += __shfl_xor_sync(0xffffffffu, o1, m);
    }
    if (lane == 0) {
        out[n * 2 + 0] = o0 + __ldg(bd2 + 0);
        out[n * 2 + 1] = o1 + __ldg(bd2 + 1);
    }
}

// ================= launch ====================================================
extern "C" void kernel_launch(void* const* d_in, const int* in_sizes, int n_in,
                              void* d_out, int out_size)
{
    const float* x    = (const float*)d_in[0];
    const int*   ei   = (const int*)  d_in[1];
    const float* ea   = (const float*)d_in[2];
    const float* Wl1  = (const float*)d_in[3];
    const float* bl1  = (const float*)d_in[4];
    const float* Wr1  = (const float*)d_in[5];
    const float* br1  = (const float*)d_in[6];
    const float* We1  = (const float*)d_in[7];
    const float* att1 = (const float*)d_in[8];
    const float* b1   = (const float*)d_in[9];
    const float* Wl2  = (const float*)d_in[10];
    const float* bl2  = (const float*)d_in[11];
    const float* Wr2  = (const float*)d_in[12];
    const float* br2  = (const float*)d_in[13];
    const float* We2  = (const float*)d_in[14];
    const float* att2 = (const float*)d_in[15];
    const float* b2   = (const float*)d_in[16];
    const float* Wd1  = (const float*)d_in[17];
    const float* bd1  = (const float*)d_in[18];
    const float* Wd2  = (const float*)d_in[19];
    const float* bd2  = (const float*)d_in[20];
    float* out = (float*)d_out;

    const int* src = ei;
    const int* dst = ei + EE;

    const int TB = 256;
    int nodeBlocks  = (NN + TB - 1) / TB;           // = NB
    int edgeBlocks  = (EE + TB - 1) / TB;
    int nodeWarpBlk = (NN * 32 + TB - 1) / TB;
    int gemmBlocks  = (NN + 63) / 64;

    // ---- CSR build (shared by both layers) ----
    zero_ideg_kernel<<<nodeBlocks, TB>>>();
    hist_kernel<<<edgeBlocks, TB>>>(dst);
    scan1_kernel<<<NB, 256>>>();
    scan2_kernel<<<1, 512>>>();
    scan3_kernel<<<NB, 256>>>();
    scatter_kernel<<<edgeBlocks, TB>>>(src, dst, ea);

    // ---- layer 1 ----
    proj_gemm<NODE_DIM, 0><<<gemmBlocks, TB>>>(x, Wl1, bl1, Wr1, br1);
    agg_kernel<<<nodeWarpBlk, TB>>>(We1, att1, b1);

    // ---- layer 2 (reads g_h inside proj) ----
    proj_gemm<HC, 1><<<gemmBlocks, TB>>>(nullptr, Wl2, bl2, Wr2, br2);
    agg_kernel<<<nodeWarpBlk, TB>>>(We2, att2, b2);

    // ---- decoder ----
    decoder_kernel<<<nodeWarpBlk, TB>>>(Wd1, bd1, Wd2, bd2, out);
}